// round 10
// baseline (speedup 1.0000x reference)
#include <cuda_runtime.h>
#include <cuda_bf16.h>
#include <cstdint>

// ---------------- problem constants ----------------
#define NUM_CHARS 128
#define UNITS     256
#define BATCH     512
#define SEQ       1024

// ---------------- decomposition ----------------
#define CPG    8       // CTAs per cluster
#define UC     32      // units per CTA
#define KDIM   256
#define NCTAS  128     // 16 clusters x 8
#define NTHREADS 256   // 8 warps: 4 m-groups x 2 n-halves
#define GB     16      // batch rows per sub-group (2 sub-groups per cluster)

// ---------------- smem layout (byte offsets) ----------------
#define OFF_MBAR   0                        // 2 mbarriers (16B)
#define OFF_AHI    1024                     // W_hi [128 m][256 k] bf16 swizzled = 64KB
#define OFF_ALO    (OFF_AHI + 65536)        // W_lo                              = 64KB
#define OFF_B0HI   (OFF_ALO + 65536)        // h_hi g0 [16 n][256 k]             = 8KB
#define OFF_B0LO   (OFF_B0HI + 8192)
#define OFF_B1HI   (OFF_B0LO + 8192)
#define OFF_B1LO   (OFF_B1HI + 8192)
#define OFF_WX     (OFF_B1LO + 8192)        // Wx fp32 [128 m][130 ch]           = 66560B
#define SMEM_TOTAL (OFF_WX + 66560)         // 231424 <= 232448

// ---------------- global scratch ----------------
__device__ unsigned g_h[2][BATCH * UNITS];   // packed (bf16 hi | bf16 lo << 16)

// ---------------- helpers ----------------
__device__ __forceinline__ uint32_t smem_u32(const void* p) {
    uint32_t a;
    asm("{ .reg .u64 t; cvta.to.shared.u64 t, %1; cvt.u32.u64 %0, t; }" : "=r"(a) : "l"(p));
    return a;
}
#define CLUSTER_SYNC() do { \
    asm volatile("barrier.cluster.arrive.aligned;" ::: "memory"); \
    asm volatile("barrier.cluster.wait.aligned;" ::: "memory"); } while (0)

#define MBARRIER_INIT(mb, c) asm volatile("mbarrier.init.shared.b64 [%0], %1;" :: "r"((uint32_t)(mb)), "r"((uint32_t)(c)) : "memory")

// remote arrive on peer CTA's barrier (release, cluster scope)
#define MBAR_ARRIVE_REMOTE(addr, rank) \
    asm volatile("{\n\t.reg .b32 ra;\n\tmapa.shared::cluster.u32 ra, %0, %1;\n\t" \
                 "mbarrier.arrive.release.cluster.shared::cluster.b64 _, [ra];\n\t}" \
                 :: "r"((uint32_t)(addr)), "r"((uint32_t)(rank)) : "memory")

// parity wait with cluster-scope acquire
#define MBAR_WAIT(mb, ph) do { \
    uint32_t _mb = (uint32_t)(mb); uint32_t _p = (uint32_t)(ph); uint32_t _done; \
    asm volatile("{\n\t.reg .pred p;\n\tmbarrier.try_wait.parity.acquire.cluster.shared::cta.b64 p, [%1], %2;\n\tselp.b32 %0, 1, 0, p;\n\t}" \
        : "=r"(_done) : "r"(_mb), "r"(_p) : "memory"); \
    if (!_done) { \
        asm volatile("{\n\t.reg .pred P1;\n\tWL_%=:\n\tmbarrier.try_wait.parity.acquire.cluster.shared::cta.b64 P1, [%0], %1, 0x989680;\n\t@P1 bra.uni WD_%=;\n\tbra.uni WL_%=;\n\tWD_%=:\n\t}" \
            :: "r"(_mb), "r"(_p) : "memory"); \
    } } while (0)

// row-major tile, 512B row stride, 16B chunks XOR-swizzled by row%8
__device__ __forceinline__ uint32_t swz(int row, int k) {
    return (uint32_t)row * 512u
         + (((((uint32_t)k >> 3) << 4)) ^ (((uint32_t)row & 7u) << 4))
         + (((uint32_t)k & 7u) << 1);
}

__device__ __forceinline__ void ldsm_x4(uint32_t r[4], uint32_t addr) {
    asm volatile("ldmatrix.sync.aligned.m8n8.x4.shared.b16 {%0,%1,%2,%3}, [%4];"
                 : "=r"(r[0]), "=r"(r[1]), "=r"(r[2]), "=r"(r[3]) : "r"(addr));
}
__device__ __forceinline__ void ldsm_x2(uint32_t r[2], uint32_t addr) {
    asm volatile("ldmatrix.sync.aligned.m8n8.x2.shared.b16 {%0,%1}, [%2];"
                 : "=r"(r[0]), "=r"(r[1]) : "r"(addr));
}

__device__ __forceinline__ void mma_bf16(float c[4],
                                         uint32_t a0, uint32_t a1, uint32_t a2, uint32_t a3,
                                         uint32_t b0, uint32_t b1) {
    asm volatile("mma.sync.aligned.m16n8k16.row.col.f32.bf16.bf16.f32 "
                 "{%0,%1,%2,%3}, {%4,%5,%6,%7}, {%8,%9}, {%0,%1,%2,%3};"
                 : "+f"(c[0]), "+f"(c[1]), "+f"(c[2]), "+f"(c[3])
                 : "r"(a0), "r"(a1), "r"(a2), "r"(a3), "r"(b0), "r"(b1));
}

__device__ __forceinline__ float sigm(float x) { return 1.0f / (1.0f + __expf(-x)); }
__device__ __forceinline__ float tanh_fast(float x) { float e = __expf(2.0f * x); return 1.0f - 2.0f / (e + 1.0f); }

__global__ void init_kernel() {
    int i = blockIdx.x * blockDim.x + threadIdx.x;
    for (; i < BATCH * UNITS; i += gridDim.x * blockDim.x) g_h[0][i] = 0u;
}

// ---------------- main persistent kernel ----------------
__global__ void __launch_bounds__(NTHREADS, 1) __cluster_dims__(CPG, 1, 1)
lstm_kernel(const int* __restrict__ tokens,
            const float* __restrict__ Wx,
            const float* __restrict__ Wh,
            const float* __restrict__ bias,
            const float* __restrict__ Wd,
            const float* __restrict__ bd,
            float* __restrict__ out) {
    extern __shared__ __align__(1024) char smem[];
    const uint32_t sb = smem_u32(smem);
    const int tid = threadIdx.x;
    const int w   = tid >> 5;
    const int L   = tid & 31;
    const int mg  = w & 3;               // m-group (32 rows)
    const int nh  = w >> 2;              // n-half (8 of 16 cols)
    const int cl  = blockIdx.x >> 3;     // cluster id 0..15
    const int r   = blockIdx.x & 7;      // cluster rank
    const int gb0 = cl * 32;             // sub-group 0 batch base
    const int gb1 = cl * 32 + 16;        // sub-group 1 batch base

    const uint32_t mbar0 = sb + OFF_MBAR;
    const uint32_t mbar1 = sb + OFF_MBAR + 8;

    float* wx_s = (float*)(smem + OFF_WX);

    if (tid == 0) { MBARRIER_INIT(mbar0, 8); MBARRIER_INIT(mbar1, 8); }

    // ---- prologue: W_h (fp32->bf16 hi/lo), Wx fp32 slice, zero B tiles ----
    {
        const int m  = tid & 127;
        const int kh = tid >> 7;
        const int rw = m & 31;
        const int gate = rw >> 3;
        const int ulocal = (m >> 5) * 8 + (rw & 7);
        const int col = gate * 256 + r * UC + ulocal;
        for (int k = kh * 128; k < kh * 128 + 128; k++) {
            float wv = Wh[k * 1024 + col];
            __nv_bfloat16 hi = __float2bfloat16(wv);
            float rem = wv - __bfloat162float(hi);
            __nv_bfloat16 lo = __float2bfloat16(rem);
            uint32_t s = swz(m, k);
            *(__nv_bfloat16*)(smem + OFF_AHI + s) = hi;
            *(__nv_bfloat16*)(smem + OFF_ALO + s) = lo;
        }
        for (int ch = kh * 64; ch < kh * 64 + 64; ch++)
            wx_s[(gate * 32 + ulocal) * 130 + ch] = Wx[ch * 1024 + col];
        // zero all 4 B tiles (h(0) = 0): 32KB
        for (int i = tid; i < 8192; i += NTHREADS)
            ((uint32_t*)(smem + OFF_B0HI))[i] = 0u;
    }

    // per-lane owned unit + bias regs
    const int ul = mg * 8 + (L >> 2);
    const float bi = bias[0 * 256 + r * UC + ul];
    const float bj = bias[1 * 256 + r * UC + ul];
    const float bf = bias[2 * 256 + r * UC + ul];
    const float bo = bias[3 * 256 + r * UC + ul];
    const float* wxi = &wx_s[(0 * 32 + ul) * 130];
    const float* wxj = &wx_s[(1 * 32 + ul) * 130];
    const float* wxf = &wx_s[(2 * 32 + ul) * 130];
    const float* wxo = &wx_s[(3 * 32 + ul) * 130];

    // ---- ldmatrix addresses ----
    const int rA   = (L & 7) + 8 * ((L >> 3) & 1);
    const uint32_t koffA = (L >> 4) ? 16u : 0u;
    const int rowA0 = mg * 32 + rA;
    const int rowA1 = rowA0 + 16;
    const uint32_t xA = ((uint32_t)rowA0 & 7u) << 4;
    const uint32_t aHi0 = sb + OFF_AHI + rowA0 * 512u;
    const uint32_t aHi1 = sb + OFF_AHI + rowA1 * 512u;
    const uint32_t aLo0 = sb + OFF_ALO + rowA0 * 512u;
    const uint32_t aLo1 = sb + OFF_ALO + rowA1 * 512u;
    const int L16 = L & 15;
    const int rB = L16 & 7;
    const uint32_t koffB = ((L16 >> 3) & 1) ? 16u : 0u;
    const int nB = nh * 8 + rB;          // row within 16-row B tile
    const uint32_t xB = ((uint32_t)rB & 7u) << 4;
    const uint32_t b0Hi = sb + OFF_B0HI + nB * 512u;
    const uint32_t b0Lo = sb + OFF_B0LO + nB * 512u;
    const uint32_t b1Hi = sb + OFF_B1HI + nB * 512u;
    const uint32_t b1Lo = sb + OFF_B1LO + nB * 512u;

    // per-lane batch cols within a 16-row sub-group: col = nh*8 + (L&3)*2 + j
    const int bc0 = nh * 8 + (L & 3) * 2;

    float c_reg[2][2] = {{0.f, 0.f}, {0.f, 0.f}};
    float wvi[2][2], wvj[2][2], wvf[2][2], wvo[2][2];

    __syncthreads();
    CLUSTER_SYNC();   // mbarrier inits + prologue visible cluster-wide

    // t=0 token/Wx prefetch for both sub-groups
#pragma unroll
    for (int g = 0; g < 2; g++) {
        const int gb = g ? gb1 : gb0;
#pragma unroll
        for (int j = 0; j < 2; j++) {
            int tk = __ldg(&tokens[(gb + bc0 + j) * SEQ + 0]);
            wvi[g][j] = wxi[tk]; wvj[g][j] = wxj[tk]; wvf[g][j] = wxf[tk]; wvo[g][j] = wxo[tk];
        }
    }

    // ---- 1024 steps, two interleaved chains ----
    for (int t = 0; t < SEQ; t++) {
        // ======== sub-group 0: MMA (B0 holds h0(t)) ========
        {
            float acc[2][4];
#pragma unroll
            for (int mt = 0; mt < 2; mt++)
#pragma unroll
                for (int e = 0; e < 4; e++) acc[mt][e] = 0.0f;
#pragma unroll 4
            for (int ks = 0; ks < 16; ks++) {
                const uint32_t ka = ((uint32_t)(ks * 32) + koffA) ^ xA;
                const uint32_t kb = ((uint32_t)(ks * 32) + koffB) ^ xB;
                uint32_t Ah0[4], Ah1[4], Al0[4], Al1[4], Bh[2], Bl[2];
                ldsm_x4(Ah0, aHi0 + ka);
                ldsm_x4(Ah1, aHi1 + ka);
                ldsm_x4(Al0, aLo0 + ka);
                ldsm_x4(Al1, aLo1 + ka);
                ldsm_x2(Bh, b0Hi + kb);
                ldsm_x2(Bl, b0Lo + kb);
                mma_bf16(acc[0], Ah0[0], Ah0[1], Ah0[2], Ah0[3], Bh[0], Bh[1]);
                mma_bf16(acc[1], Ah1[0], Ah1[1], Ah1[2], Ah1[3], Bh[0], Bh[1]);
                mma_bf16(acc[0], Ah0[0], Ah0[1], Ah0[2], Ah0[3], Bl[0], Bl[1]);
                mma_bf16(acc[1], Ah1[0], Ah1[1], Ah1[2], Ah1[3], Bl[0], Bl[1]);
                mma_bf16(acc[0], Al0[0], Al0[1], Al0[2], Al0[3], Bh[0], Bh[1]);
                mma_bf16(acc[1], Al1[0], Al1[1], Al1[2], Al1[3], Bh[0], Bh[1]);
            }
            // elementwise + store h0(t+1)
            unsigned* dst = &g_h[(t + 1) & 1][0];
#pragma unroll
            for (int j = 0; j < 2; j++) {
                float gi = acc[0][j]     + wvi[0][j] + bi;
                float gj = acc[0][2 + j] + wvj[0][j] + bj;
                float gf = acc[1][j]     + wvf[0][j] + bf;
                float go = acc[1][2 + j] + wvo[0][j] + bo;
                float nc = c_reg[0][j] * sigm(gf + 1.0f) + sigm(gi) * tanh_fast(gj);
                c_reg[0][j] = nc;
                float nh2 = tanh_fast(nc) * sigm(go);
                __nv_bfloat16 hi = __float2bfloat16(nh2);
                float rem = nh2 - __bfloat162float(hi);
                __nv_bfloat16 lo = __float2bfloat16(rem);
                unsigned pk = (unsigned)__bfloat16_as_ushort(hi) | ((unsigned)__bfloat16_as_ushort(lo) << 16);
                __stcg(&dst[(gb0 + bc0 + j) * UNITS + r * UC + ul], pk);
            }
        }
        __syncthreads();                       // all h0 stores + B0/B1 reads done
        if (tid == 0) {
#pragma unroll
            for (int d = 0; d < CPG; d++) MBAR_ARRIVE_REMOTE(mbar0, d);
        }
        // prefetch g0 tokens for t+1 (shadow)
        {
            const int tp = (t + 1 < SEQ) ? (t + 1) : (SEQ - 1);
#pragma unroll
            for (int j = 0; j < 2; j++) {
                int tk = __ldg(&tokens[(gb0 + bc0 + j) * SEQ + tp]);
                wvi[0][j] = wxi[tk]; wvj[0][j] = wxj[tk]; wvf[0][j] = wxf[tk]; wvo[0][j] = wxo[tk];
            }
        }

        // ======== sub-group 1: wait + load B1 = h1(t) ========
        if (t > 0) {
            MBAR_WAIT(mbar1, (t - 1) & 1);
            const uint4* src = (const uint4*)&g_h[t & 1][gb1 * UNITS];
#pragma unroll
            for (int ii = 0; ii < 4; ii++) {
                int idx4 = tid + (ii << 8);        // 1024 uint4 = 16 rows
                uint4 p = __ldcg(src + idx4);
                int n  = idx4 >> 6;
                int k4 = (idx4 & 63) << 2;
                uint32_t hi01 = (p.x & 0xFFFFu) | (p.y << 16);
                uint32_t hi23 = (p.z & 0xFFFFu) | (p.w << 16);
                uint32_t lo01 = (p.x >> 16) | (p.y & 0xFFFF0000u);
                uint32_t lo23 = (p.z >> 16) | (p.w & 0xFFFF0000u);
                uint32_t s = swz(n, k4);
                *(uint2*)(smem + OFF_B1HI + s) = make_uint2(hi01, hi23);
                *(uint2*)(smem + OFF_B1LO + s) = make_uint2(lo01, lo23);
            }
        }
        __syncthreads();

        // ======== sub-group 1: MMA + elementwise + store h1(t+1) ========
        {
            float acc[2][4];
#pragma unroll
            for (int mt = 0; mt < 2; mt++)
#pragma unroll
                for (int e = 0; e < 4; e++) acc[mt][e] = 0.0f;
#pragma unroll 4
            for (int ks = 0; ks < 16; ks++) {
                const uint32_t ka = ((uint32_t)(ks * 32) + koffA) ^ xA;
                const uint32_t kb = ((uint32_t)(ks * 32) + koffB) ^ xB;
                uint32_t Ah0[4], Ah1[4], Al0[4], Al1[4], Bh[2], Bl[2];
                ldsm_x4(Ah0, aHi0 + ka);
                ldsm_x4(Ah1, aHi1 + ka);
                ldsm_x4(Al0, aLo0 + ka);
                ldsm_x4(Al1, aLo1 + ka);
                ldsm_x2(Bh, b1Hi + kb);
                ldsm_x2(Bl, b1Lo + kb);
                mma_bf16(acc[0], Ah0[0], Ah0[1], Ah0[2], Ah0[3], Bh[0], Bh[1]);
                mma_bf16(acc[1], Ah1[0], Ah1[1], Ah1[2], Ah1[3], Bh[0], Bh[1]);
                mma_bf16(acc[0], Ah0[0], Ah0[1], Ah0[2], Ah0[3], Bl[0], Bl[1]);
                mma_bf16(acc[1], Ah1[0], Ah1[1], Ah1[2], Ah1[3], Bl[0], Bl[1]);
                mma_bf16(acc[0], Al0[0], Al0[1], Al0[2], Al0[3], Bh[0], Bh[1]);
                mma_bf16(acc[1], Al1[0], Al1[1], Al1[2], Al1[3], Bh[0], Bh[1]);
            }
            unsigned* dst = &g_h[(t + 1) & 1][0];
#pragma unroll
            for (int j = 0; j < 2; j++) {
                float gi = acc[0][j]     + wvi[1][j] + bi;
                float gj = acc[0][2 + j] + wvj[1][j] + bj;
                float gf = acc[1][j]     + wvf[1][j] + bf;
                float go = acc[1][2 + j] + wvo[1][j] + bo;
                float nc = c_reg[1][j] * sigm(gf + 1.0f) + sigm(gi) * tanh_fast(gj);
                c_reg[1][j] = nc;
                float nh2 = tanh_fast(nc) * sigm(go);
                __nv_bfloat16 hi = __float2bfloat16(nh2);
                float rem = nh2 - __bfloat162float(hi);
                __nv_bfloat16 lo = __float2bfloat16(rem);
                unsigned pk = (unsigned)__bfloat16_as_ushort(hi) | ((unsigned)__bfloat16_as_ushort(lo) << 16);
                __stcg(&dst[(gb1 + bc0 + j) * UNITS + r * UC + ul], pk);
            }
        }
        __syncthreads();                       // all h1 stores + B1 reads done
        if (tid == 0) {
#pragma unroll
            for (int d = 0; d < CPG; d++) MBAR_ARRIVE_REMOTE(mbar1, d);
        }
        // prefetch g1 tokens for t+1 (shadow)
        {
            const int tp = (t + 1 < SEQ) ? (t + 1) : (SEQ - 1);
#pragma unroll
            for (int j = 0; j < 2; j++) {
                int tk = __ldg(&tokens[(gb1 + bc0 + j) * SEQ + tp]);
                wvi[1][j] = wxi[tk]; wvj[1][j] = wxj[tk]; wvf[1][j] = wxf[tk]; wvo[1][j] = wxo[tk];
            }
        }

        // ======== sub-group 0: wait + load B0 = h0(t+1) (covered by g1 work above) ========
        {
            MBAR_WAIT(mbar0, t & 1);
            const uint4* src = (const uint4*)&g_h[(t + 1) & 1][gb0 * UNITS];
#pragma unroll
            for (int ii = 0; ii < 4; ii++) {
                int idx4 = tid + (ii << 8);
                uint4 p = __ldcg(src + idx4);
                int n  = idx4 >> 6;
                int k4 = (idx4 & 63) << 2;
                uint32_t hi01 = (p.x & 0xFFFFu) | (p.y << 16);
                uint32_t hi23 = (p.z & 0xFFFFu) | (p.w << 16);
                uint32_t lo01 = (p.x >> 16) | (p.y & 0xFFFF0000u);
                uint32_t lo23 = (p.z >> 16) | (p.w & 0xFFFF0000u);
                uint32_t s = swz(n, k4);
                *(uint2*)(smem + OFF_B0HI + s) = make_uint2(hi01, hi23);
                *(uint2*)(smem + OFF_B0LO + s) = make_uint2(lo01, lo23);
            }
        }
        __syncthreads();
    }

    // ---- dense head (h(1024) in g_h[0]; mbar0 phase 1023 already consumed in-loop) ----
    MBAR_WAIT(mbar1, 1);      // final g1 stores visible
    __syncthreads();
    {
        float* hs = (float*)(smem + OFF_AHI);   // reuse: 4 rows x 256 fp32
        const int bstart = r * 4;
        for (int i = tid; i < 4 * UNITS; i += NTHREADS) {
            unsigned p = __ldcg(&g_h[0][(cl * 32 + bstart + (i >> 8)) * UNITS + (i & 255)]);
            hs[i] = __bfloat162float(__ushort_as_bfloat16((unsigned short)(p & 0xFFFFu))) +
                    __bfloat162float(__ushort_as_bfloat16((unsigned short)(p >> 16)));
        }
        __syncthreads();
        const int n    = tid & 127;
        const int pair = tid >> 7;
        float a0 = bd[n], a1 = bd[n];
        for (int k = 0; k < UNITS; k++) {
            float wv = Wd[k * NUM_CHARS + n];
            a0 += hs[(pair * 2 + 0) * 256 + k] * wv;
            a1 += hs[(pair * 2 + 1) * 256 + k] * wv;
        }
        out[(cl * 32 + bstart + pair * 2 + 0) * NUM_CHARS + n] = a0;
        out[(cl * 32 + bstart + pair * 2 + 1) * NUM_CHARS + n] = a1;
    }
    CLUSTER_SYNC();
}

// ---------------- host launcher ----------------
extern "C" void kernel_launch(void* const* d_in, const int* in_sizes, int n_in,
                              void* d_out, int out_size) {
    (void)in_sizes; (void)n_in; (void)out_size;
    const int*   tokens = (const int*)d_in[0];
    const float* Wx     = (const float*)d_in[1];
    const float* Wh     = (const float*)d_in[2];
    const float* b      = (const float*)d_in[3];
    const float* Wd     = (const float*)d_in[4];
    const float* bdn    = (const float*)d_in[5];
    float* out = (float*)d_out;

    cudaFuncSetAttribute(lstm_kernel, cudaFuncAttributeMaxDynamicSharedMemorySize, SMEM_TOTAL);

    init_kernel<<<256, 256>>>();
    lstm_kernel<<<NCTAS, NTHREADS, SMEM_TOTAL>>>(tokens, Wx, Wh, b, Wd, bdn, out);
}

// round 11
// speedup vs baseline: 2.6331x; 2.6331x over previous
#include <cuda_runtime.h>
#include <cuda_bf16.h>
#include <cstdint>

// ---------------- problem constants ----------------
#define NUM_CHARS 128
#define UNITS     256
#define BATCH     512
#define SEQ       1024

// ---------------- decomposition ----------------
#define GROUPS 16      // batch groups (= clusters)
#define CPG    8       // CTAs per group (cluster size)
#define MBATCH 32      // batch rows per group
#define UC     32      // units per CTA
#define KDIM   256     // h dimension (MMA K)
#define NCTAS  (GROUPS*CPG)
#define NTHREADS 256   // 8 warps: 4 m-groups x 2 n-halves

// ---------------- smem layout (byte offsets) ----------------
#define OFF_AHI    1024                     // W_hi slice [128 m][256 k] bf16 swizzled = 64KB
#define OFF_ALO    (OFF_AHI + 65536)        // W_lo slice                              = 64KB
#define OFF_BHI    (OFF_ALO + 65536)        // h_hi tile [32 n][256 k] bf16 swizzled   = 16KB
#define OFF_BLO    (OFF_BHI + 16384)        // h_lo tile                               = 16KB
#define OFF_WX     (OFF_BLO + 16384)        // Wx slice fp32 [128 m][130 ch]           = 66560B
#define SMEM_TOTAL (OFF_WX + 66560)

// ---------------- global scratch ----------------
__device__ unsigned g_h[2][BATCH * UNITS];   // packed (bf16 hi | bf16 lo << 16), double-buffered

// ---------------- helpers ----------------
__device__ __forceinline__ uint32_t smem_u32(const void* p) {
    uint32_t a;
    asm("{ .reg .u64 t; cvta.to.shared.u64 t, %1; cvt.u32.u64 %0, t; }" : "=r"(a) : "l"(p));
    return a;
}
#define CLUSTER_ARRIVE() asm volatile("barrier.cluster.arrive.aligned;" ::: "memory")
#define CLUSTER_WAIT()   asm volatile("barrier.cluster.wait.aligned;" ::: "memory")

// row-major tile, 512B row stride, 16B chunks XOR-swizzled by row%8 (conflict-free ldmatrix)
__device__ __forceinline__ uint32_t swz(int row, int k) {
    return (uint32_t)row * 512u
         + (((((uint32_t)k >> 3) << 4)) ^ (((uint32_t)row & 7u) << 4))
         + (((uint32_t)k & 7u) << 1);
}

__device__ __forceinline__ void ldsm_x4(uint32_t r[4], uint32_t addr) {
    asm volatile("ldmatrix.sync.aligned.m8n8.x4.shared.b16 {%0,%1,%2,%3}, [%4];"
                 : "=r"(r[0]), "=r"(r[1]), "=r"(r[2]), "=r"(r[3]) : "r"(addr));
}

__device__ __forceinline__ void mma_bf16(float c[4],
                                         uint32_t a0, uint32_t a1, uint32_t a2, uint32_t a3,
                                         uint32_t b0, uint32_t b1) {
    asm volatile("mma.sync.aligned.m16n8k16.row.col.f32.bf16.bf16.f32 "
                 "{%0,%1,%2,%3}, {%4,%5,%6,%7}, {%8,%9}, {%0,%1,%2,%3};"
                 : "+f"(c[0]), "+f"(c[1]), "+f"(c[2]), "+f"(c[3])
                 : "r"(a0), "r"(a1), "r"(a2), "r"(a3), "r"(b0), "r"(b1));
}

// guaranteed-fast activations: explicit MUFU (same units __expf uses -> same numerics)
__device__ __forceinline__ float ex2f(float x) { float y; asm("ex2.approx.ftz.f32 %0, %1;" : "=f"(y) : "f"(x)); return y; }
__device__ __forceinline__ float rcpf(float x) { float y; asm("rcp.approx.ftz.f32 %0, %1;" : "=f"(y) : "f"(x)); return y; }
#define LOG2E 1.4426950408889634f
__device__ __forceinline__ float sigm(float x) { return rcpf(1.0f + ex2f(-LOG2E * x)); }
__device__ __forceinline__ float tanh_fast(float x) { return 1.0f - 2.0f * rcpf(ex2f(2.0f * LOG2E * x) + 1.0f); }

// ---------------- init kernel: zero g_h[0] ----------------
__global__ void init_kernel() {
    int i = blockIdx.x * blockDim.x + threadIdx.x;
    for (; i < BATCH * UNITS; i += gridDim.x * blockDim.x) g_h[0][i] = 0u;
}

// ---------------- main persistent kernel ----------------
__global__ void __launch_bounds__(NTHREADS, 1) __cluster_dims__(CPG, 1, 1)
lstm_kernel(const int* __restrict__ tokens,
            const float* __restrict__ Wx,
            const float* __restrict__ Wh,
            const float* __restrict__ bias,
            const float* __restrict__ Wd,
            const float* __restrict__ bd,
            float* __restrict__ out) {
    extern __shared__ __align__(1024) char smem[];
    const uint32_t sb = smem_u32(smem);
    const int tid = threadIdx.x;
    const int w   = tid >> 5;            // warp 0..7
    const int L   = tid & 31;
    const int mg  = w & 3;               // m-group (0..3): 32 m-rows
    const int nh  = w >> 2;              // n-half  (0..1): 16 n-cols
    const int group = blockIdx.x >> 3;
    const int r     = blockIdx.x & 7;    // cluster rank
    const int gbase = group * MBATCH;

    float* wx_s = (float*)(smem + OFF_WX);

    // ---- prologue: W_h slice (fp32 -> bf16 hi/lo), Wx fp32 slice ----
    {
        const int m  = tid & 127;
        const int kh = tid >> 7;                  // k/ch half
        const int rw = m & 31;
        const int gate = rw >> 3;
        const int ulocal = (m >> 5) * 8 + (rw & 7);
        const int col = gate * 256 + r * UC + ulocal;
        for (int k = kh * 128; k < kh * 128 + 128; k++) {
            float wv = Wh[k * 1024 + col];
            __nv_bfloat16 hi = __float2bfloat16(wv);
            float rem = wv - __bfloat162float(hi);
            __nv_bfloat16 lo = __float2bfloat16(rem);
            uint32_t s = swz(m, k);
            *(__nv_bfloat16*)(smem + OFF_AHI + s) = hi;
            *(__nv_bfloat16*)(smem + OFF_ALO + s) = lo;
        }
        for (int ch = kh * 64; ch < kh * 64 + 64; ch++)
            wx_s[(gate * 32 + ulocal) * 130 + ch] = Wx[ch * 1024 + col];
    }

    // per-lane owned unit + bias regs
    const int ul = mg * 8 + (L >> 2);            // unit local 0..31
    const float bi = bias[0 * 256 + r * UC + ul];
    const float bj = bias[1 * 256 + r * UC + ul];
    const float bf = bias[2 * 256 + r * UC + ul];
    const float bo = bias[3 * 256 + r * UC + ul];
    const float* wxi = &wx_s[(0 * 32 + ul) * 130];
    const float* wxj = &wx_s[(1 * 32 + ul) * 130];
    const float* wxf = &wx_s[(2 * 32 + ul) * 130];
    const float* wxo = &wx_s[(3 * 32 + ul) * 130];

    // ---- per-lane ldmatrix addresses ----
    const int rA   = (L & 7) + 8 * ((L >> 3) & 1);
    const uint32_t koffA = (L >> 4) ? 16u : 0u;
    const int rowA0 = mg * 32 + rA;
    const int rowA1 = rowA0 + 16;
    const uint32_t xA = ((uint32_t)rowA0 & 7u) << 4;
    const uint32_t aHi0 = sb + OFF_AHI + rowA0 * 512u;
    const uint32_t aHi1 = sb + OFF_AHI + rowA1 * 512u;
    const uint32_t aLo0 = sb + OFF_ALO + rowA0 * 512u;
    const uint32_t aLo1 = sb + OFF_ALO + rowA1 * 512u;
    const int rB = L & 7;
    const uint32_t koffB = ((L >> 3) & 1) ? 16u : 0u;
    const int nB = nh * 16 + ((L >> 4) & 1) * 8 + rB;    // 16 n-rows for this n-half
    const uint32_t xB = ((uint32_t)rB & 7u) << 4;
    const uint32_t bHi = sb + OFF_BHI + nB * 512u;
    const uint32_t bLo = sb + OFF_BLO + nB * 512u;

    // per-lane batch columns: bb(e) = nh*16 + nb*8 + (L&3)*2 + j, e = nb*2+j
    int bbs[4];
#pragma unroll
    for (int nb = 0; nb < 2; nb++)
#pragma unroll
        for (int j = 0; j < 2; j++) bbs[nb * 2 + j] = nh * 16 + nb * 8 + (L & 3) * 2 + j;

    float c_reg[4];
#pragma unroll
    for (int k = 0; k < 4; k++) c_reg[k] = 0.0f;

    __syncthreads();          // wx_s / A tiles written

    // ---- A_hi register-stationary: load all 128 fragments once ----
    uint32_t AH0[16][4], AH1[16][4];
#pragma unroll
    for (int ks = 0; ks < 16; ks++) {
        const uint32_t ka = ((uint32_t)(ks * 32) + koffA) ^ xA;
        ldsm_x4(AH0[ks], aHi0 + ka);
        ldsm_x4(AH1[ks], aHi1 + ka);
    }

    CLUSTER_ARRIVE();         // phase 0 (prologue done; init_kernel zeros already visible)

    // prefetch tokens + Wx gather for t=0 (runs in barrier-skew shadow)
    float wvi[4], wvj[4], wvf[4], wvo[4];
#pragma unroll
    for (int e = 0; e < 4; e++) {
        int tk = __ldg(&tokens[(gbase + bbs[e]) * SEQ + 0]);
        wvi[e] = wxi[tk]; wvj[e] = wxj[tk]; wvf[e] = wxf[tk]; wvo[e] = wxo[tk];
    }

    // ---- 1024 recurrent steps ----
    for (int t = 0; t < SEQ; t++) {
        CLUSTER_WAIT();   // all CTAs' h stores for step t visible; also CTA-wide barrier

        // load h (packed bf16 hi/lo), unpack into swizzled Bhi/Blo
        {
            const uint4* src = (const uint4*)&g_h[t & 1][gbase * UNITS];
#pragma unroll
            for (int ii = 0; ii < 8; ii++) {
                int idx4 = tid + (ii << 8);
                uint4 p = __ldcg(src + idx4);
                int n  = idx4 >> 6;
                int k4 = (idx4 & 63) << 2;
                uint32_t hi01 = (p.x & 0xFFFFu) | (p.y << 16);
                uint32_t hi23 = (p.z & 0xFFFFu) | (p.w << 16);
                uint32_t lo01 = (p.x >> 16) | (p.y & 0xFFFF0000u);
                uint32_t lo23 = (p.z >> 16) | (p.w & 0xFFFF0000u);
                uint32_t s = swz(n, k4);
                *(uint2*)(smem + OFF_BHI + s) = make_uint2(hi01, hi23);
                *(uint2*)(smem + OFF_BLO + s) = make_uint2(lo01, lo23);
            }
        }
        __syncthreads();

        // ---- MMA: gates = Whi*hhi + Whi*hlo + Wlo*hhi over K=256; A_hi resident ----
        float acc[2][2][4];
#pragma unroll
        for (int mt = 0; mt < 2; mt++)
#pragma unroll
            for (int nb = 0; nb < 2; nb++)
#pragma unroll
                for (int e = 0; e < 4; e++) acc[mt][nb][e] = 0.0f;

#pragma unroll
        for (int ks = 0; ks < 16; ks++) {
            const uint32_t ka = ((uint32_t)(ks * 32) + koffA) ^ xA;
            const uint32_t kb = ((uint32_t)(ks * 32) + koffB) ^ xB;
            uint32_t Al0[4], Al1[4], Bh[4], Bl[4];
            ldsm_x4(Bh, bHi + kb);   // regs {0,1}=n-block 0, {2,3}=n-block 1
            ldsm_x4(Al0, aLo0 + ka);
            ldsm_x4(Al1, aLo1 + ka);
            ldsm_x4(Bl, bLo + kb);
#pragma unroll
            for (int nb = 0; nb < 2; nb++) {
                // pass 1: Whi x hhi (A resident)
                mma_bf16(acc[0][nb], AH0[ks][0], AH0[ks][1], AH0[ks][2], AH0[ks][3], Bh[2 * nb], Bh[2 * nb + 1]);
                mma_bf16(acc[1][nb], AH1[ks][0], AH1[ks][1], AH1[ks][2], AH1[ks][3], Bh[2 * nb], Bh[2 * nb + 1]);
                // pass 3: Wlo x hhi
                mma_bf16(acc[0][nb], Al0[0], Al0[1], Al0[2], Al0[3], Bh[2 * nb], Bh[2 * nb + 1]);
                mma_bf16(acc[1][nb], Al1[0], Al1[1], Al1[2], Al1[3], Bh[2 * nb], Bh[2 * nb + 1]);
                // pass 2: Whi x hlo (A resident)
                mma_bf16(acc[0][nb], AH0[ks][0], AH0[ks][1], AH0[ks][2], AH0[ks][3], Bl[2 * nb], Bl[2 * nb + 1]);
                mma_bf16(acc[1][nb], AH1[ks][0], AH1[ks][1], AH1[ks][2], AH1[ks][3], Bl[2 * nb], Bl[2 * nb + 1]);
            }
        }

        // ---- LSTM elementwise in registers (lane owns unit ul, 4 batch cols) ----
        {
            unsigned* dst = &g_h[(t + 1) & 1][0];
#pragma unroll
            for (int nb = 0; nb < 2; nb++) {
#pragma unroll
                for (int j = 0; j < 2; j++) {
                    const int e = nb * 2 + j;
                    float gi = acc[0][nb][j]     + wvi[e] + bi;
                    float gj = acc[0][nb][2 + j] + wvj[e] + bj;
                    float gf = acc[1][nb][j]     + wvf[e] + bf;
                    float go = acc[1][nb][2 + j] + wvo[e] + bo;
                    float nc = c_reg[e] * sigm(gf + 1.0f) + sigm(gi) * tanh_fast(gj);
                    c_reg[e] = nc;
                    float nh2 = tanh_fast(nc) * sigm(go);
                    __nv_bfloat16 hi = __float2bfloat16(nh2);
                    float rem = nh2 - __bfloat162float(hi);
                    __nv_bfloat16 lo = __float2bfloat16(rem);
                    unsigned packed = (unsigned)__bfloat16_as_ushort(hi) | ((unsigned)__bfloat16_as_ushort(lo) << 16);
                    __stcg(&dst[(gbase + bbs[e]) * UNITS + r * UC + ul], packed);
                }
            }
        }
        CLUSTER_ARRIVE();   // my h(t+1) stores issued & ordered (release)

        // prefetch next step's tokens + Wx gather in the skew shadow
        {
            const int tp = (t + 1 < SEQ) ? (t + 1) : (SEQ - 1);
#pragma unroll
            for (int e = 0; e < 4; e++) {
                int tk = __ldg(&tokens[(gbase + bbs[e]) * SEQ + tp]);
                wvi[e] = wxi[tk]; wvj[e] = wxj[tk]; wvf[e] = wxf[tk]; wvo[e] = wxo[tk];
            }
        }
    }

    // ---- dense head: logits = h @ W_dense + b_dense (final h in g_h[0]) ----
    CLUSTER_WAIT();   // final h stores visible; CTA-wide barrier (safe to reuse AHI smem)
    {
        float* hs = (float*)(smem + OFF_AHI);   // reuse A region: 4 rows x 256 fp32
        const int bstart = r * 4;
        for (int i = tid; i < 4 * UNITS; i += NTHREADS) {
            unsigned p = __ldcg(&g_h[0][(gbase + bstart + (i >> 8)) * UNITS + (i & 255)]);
            hs[i] = __bfloat162float(__ushort_as_bfloat16((unsigned short)(p & 0xFFFFu))) +
                    __bfloat162float(__ushort_as_bfloat16((unsigned short)(p >> 16)));
        }
        __syncthreads();
        const int n    = tid & 127;   // output char
        const int pair = tid >> 7;    // 2 batch rows each
        float a0 = bd[n], a1 = bd[n];
        for (int k = 0; k < UNITS; k++) {
            float wv = Wd[k * NUM_CHARS + n];
            a0 += hs[(pair * 2 + 0) * 256 + k] * wv;
            a1 += hs[(pair * 2 + 1) * 256 + k] * wv;
        }
        out[(gbase + bstart + pair * 2 + 0) * NUM_CHARS + n] = a0;
        out[(gbase + bstart + pair * 2 + 1) * NUM_CHARS + n] = a1;
    }
}

// ---------------- host launcher ----------------
extern "C" void kernel_launch(void* const* d_in, const int* in_sizes, int n_in,
                              void* d_out, int out_size) {
    (void)in_sizes; (void)n_in; (void)out_size;
    const int*   tokens = (const int*)d_in[0];
    const float* Wx     = (const float*)d_in[1];
    const float* Wh     = (const float*)d_in[2];
    const float* b      = (const float*)d_in[3];
    const float* Wd     = (const float*)d_in[4];
    const float* bdn    = (const float*)d_in[5];
    float* out = (float*)d_out;

    cudaFuncSetAttribute(lstm_kernel, cudaFuncAttributeMaxDynamicSharedMemorySize, SMEM_TOTAL);

    init_kernel<<<256, 256>>>();
    lstm_kernel<<<NCTAS, NTHREADS, SMEM_TOTAL>>>(tokens, Wx, Wh, b, Wd, bdn, out);
}

// round 13
// speedup vs baseline: 2.6425x; 1.0036x over previous
#include <cuda_runtime.h>
#include <cuda_bf16.h>
#include <cstdint>

// ---------------- problem constants ----------------
#define NUM_CHARS 128
#define UNITS     256
#define BATCH     512
#define SEQ       1024

// ---------------- decomposition ----------------
#define GROUPS 16
#define CPG    8
#define MBATCH 32
#define UC     32
#define KDIM   256
#define NCTAS  (GROUPS*CPG)
#define NTHREADS 256   // 8 warps: 4 m-groups x 2 n-halves

// ---------------- smem layout ----------------
#define OFF_AHI    1024
#define OFF_ALO    (OFF_AHI + 65536)
#define OFF_BHI    (OFF_ALO + 65536)
#define OFF_BLO    (OFF_BHI + 16384)
#define OFF_WX     (OFF_BLO + 16384)
#define SMEM_TOTAL (OFF_WX + 66560)

__device__ unsigned g_h[2][BATCH * UNITS];   // packed (bf16 hi | bf16 lo << 16)

// ---------------- helpers ----------------
__device__ __forceinline__ uint32_t smem_u32(const void* p) {
    uint32_t a;
    asm("{ .reg .u64 t; cvta.to.shared.u64 t, %1; cvt.u32.u64 %0, t; }" : "=r"(a) : "l"(p));
    return a;
}
#define CLUSTER_ARRIVE() asm volatile("barrier.cluster.arrive.aligned;" ::: "memory")
#define CLUSTER_WAIT()   asm volatile("barrier.cluster.wait.aligned;" ::: "memory")

__device__ __forceinline__ uint32_t swz(int row, int k) {
    return (uint32_t)row * 512u
         + (((((uint32_t)k >> 3) << 4)) ^ (((uint32_t)row & 7u) << 4))
         + (((uint32_t)k & 7u) << 1);
}

__device__ __forceinline__ void ldsm_x4(uint32_t r[4], uint32_t addr) {
    asm volatile("ldmatrix.sync.aligned.m8n8.x4.shared.b16 {%0,%1,%2,%3}, [%4];"
                 : "=r"(r[0]), "=r"(r[1]), "=r"(r[2]), "=r"(r[3]) : "r"(addr));
}

__device__ __forceinline__ void mma_bf16(float c[4],
                                         uint32_t a0, uint32_t a1, uint32_t a2, uint32_t a3,
                                         uint32_t b0, uint32_t b1) {
    asm volatile("mma.sync.aligned.m16n8k16.row.col.f32.bf16.bf16.f32 "
                 "{%0,%1,%2,%3}, {%4,%5,%6,%7}, {%8,%9}, {%0,%1,%2,%3};"
                 : "+f"(c[0]), "+f"(c[1]), "+f"(c[2]), "+f"(c[3])
                 : "r"(a0), "r"(a1), "r"(a2), "r"(a3), "r"(b0), "r"(b1));
}

__device__ __forceinline__ uint32_t prmt(uint32_t a, uint32_t b, uint32_t sel) {
    uint32_t d;
    asm("prmt.b32 %0, %1, %2, %3;" : "=r"(d) : "r"(a), "r"(b), "r"(sel));
    return d;
}

// fast activations: explicit MUFU (same units __expf uses)
__device__ __forceinline__ float ex2f(float x) { float y; asm("ex2.approx.ftz.f32 %0, %1;" : "=f"(y) : "f"(x)); return y; }
__device__ __forceinline__ float rcpf(float x) { float y; asm("rcp.approx.ftz.f32 %0, %1;" : "=f"(y) : "f"(x)); return y; }
#define LOG2E 1.4426950408889634f
__device__ __forceinline__ float sigm(float x) { return rcpf(1.0f + ex2f(-LOG2E * x)); }
__device__ __forceinline__ float tanh_fast(float x) { return 1.0f - 2.0f * rcpf(ex2f(2.0f * LOG2E * x) + 1.0f); }

__global__ void init_kernel() {
    int i = blockIdx.x * blockDim.x + threadIdx.x;
    for (; i < BATCH * UNITS; i += gridDim.x * blockDim.x) g_h[0][i] = 0u;
}

// ---------------- main persistent kernel ----------------
__global__ void __launch_bounds__(NTHREADS, 1) __cluster_dims__(CPG, 1, 1)
lstm_kernel(const int* __restrict__ tokens,
            const float* __restrict__ Wx,
            const float* __restrict__ Wh,
            const float* __restrict__ bias,
            const float* __restrict__ Wd,
            const float* __restrict__ bd,
            float* __restrict__ out) {
    extern __shared__ __align__(1024) char smem[];
    const uint32_t sb = smem_u32(smem);
    const int tid = threadIdx.x;
    const int w   = tid >> 5;
    const int L   = tid & 31;
    const int mg  = w & 3;
    const int nh  = w >> 2;
    const int group = blockIdx.x >> 3;
    const int r     = blockIdx.x & 7;
    const int gbase = group * MBATCH;

    float* wx_s = (float*)(smem + OFF_WX);

    // ---- prologue: W_h (fp32 -> bf16 hi/lo), Wx fp32 slice ----
    {
        const int m  = tid & 127;
        const int kh = tid >> 7;
        const int rw = m & 31;
        const int gate = rw >> 3;
        const int ulocal = (m >> 5) * 8 + (rw & 7);
        const int col = gate * 256 + r * UC + ulocal;
        for (int k = kh * 128; k < kh * 128 + 128; k++) {
            float wv = Wh[k * 1024 + col];
            __nv_bfloat16 hi = __float2bfloat16(wv);
            float rem = wv - __bfloat162float(hi);
            __nv_bfloat16 lo = __float2bfloat16(rem);
            uint32_t s = swz(m, k);
            *(__nv_bfloat16*)(smem + OFF_AHI + s) = hi;
            *(__nv_bfloat16*)(smem + OFF_ALO + s) = lo;
        }
        for (int ch = kh * 64; ch < kh * 64 + 64; ch++)
            wx_s[(gate * 32 + ulocal) * 130 + ch] = Wx[ch * 1024 + col];
    }

    // per-lane owned unit + bias regs
    const int ul = mg * 8 + (L >> 2);
    const float bi = bias[0 * 256 + r * UC + ul];
    const float bj = bias[1 * 256 + r * UC + ul];
    const float bf = bias[2 * 256 + r * UC + ul];
    const float bo = bias[3 * 256 + r * UC + ul];
    const float* wxi = &wx_s[(0 * 32 + ul) * 130];
    const float* wxj = &wx_s[(1 * 32 + ul) * 130];
    const float* wxf = &wx_s[(2 * 32 + ul) * 130];
    const float* wxo = &wx_s[(3 * 32 + ul) * 130];

    // ---- ldmatrix addresses ----
    const int rA   = (L & 7) + 8 * ((L >> 3) & 1);
    const uint32_t koffA = (L >> 4) ? 16u : 0u;
    const int rowA0 = mg * 32 + rA;
    const int rowA1 = rowA0 + 16;
    const uint32_t xA = ((uint32_t)rowA0 & 7u) << 4;
    const uint32_t aHi0 = sb + OFF_AHI + rowA0 * 512u;
    const uint32_t aHi1 = sb + OFF_AHI + rowA1 * 512u;
    const uint32_t aLo0 = sb + OFF_ALO + rowA0 * 512u;
    const uint32_t aLo1 = sb + OFF_ALO + rowA1 * 512u;
    const int rB = L & 7;
    const uint32_t koffB = ((L >> 3) & 1) ? 16u : 0u;
    const int nB = nh * 16 + ((L >> 4) & 1) * 8 + rB;
    const uint32_t xB = ((uint32_t)rB & 7u) << 4;
    const uint32_t bHi = sb + OFF_BHI + nB * 512u;
    const uint32_t bLo = sb + OFF_BLO + nB * 512u;

    // per-lane batch columns + precomputed global h indices
    int gidx[4];
#pragma unroll
    for (int nb = 0; nb < 2; nb++)
#pragma unroll
        for (int j = 0; j < 2; j++) {
            int bb = nh * 16 + nb * 8 + (L & 3) * 2 + j;
            gidx[nb * 2 + j] = (gbase + bb) * UNITS + r * UC + ul;
        }

    // precomputed B-store swizzle offsets (loop-invariant)
    uint32_t soff0[4], soff1[4];
#pragma unroll
    for (int ii = 0; ii < 4; ii++) {
        int nrow = (tid >> 5) + ii * 8;
        soff0[ii] = swz(nrow, (L & 31) * 4);         // half 0: elements [0,128)
        soff1[ii] = swz(nrow, 128 + (L & 31) * 4);   // half 1: elements [128,256)
    }

    float c_reg[4];
#pragma unroll
    for (int k = 0; k < 4; k++) c_reg[k] = 0.0f;

    __syncthreads();

    // ---- A_hi m-tile0 register-stationary (AH1 streams) ----
    uint32_t AH0[16][4];
#pragma unroll
    for (int ks = 0; ks < 16; ks++) {
        const uint32_t ka = ((uint32_t)(ks * 32) + koffA) ^ xA;
        ldsm_x4(AH0[ks], aHi0 + ka);
    }

    CLUSTER_ARRIVE();

    // prefetch tokens + Wx gather for t=0
    float wvi[4], wvj[4], wvf[4], wvo[4];
#pragma unroll
    for (int e = 0; e < 4; e++) {
        int bb = nh * 16 + ((e >> 1) ? 8 : 0) + (L & 3) * 2 + (e & 1);
        int tk = __ldg(&tokens[(gbase + bb) * SEQ + 0]);
        wvi[e] = wxi[tk]; wvj[e] = wxj[tk]; wvf[e] = wxf[tk]; wvo[e] = wxo[tk];
    }

    // ---- 1024 recurrent steps ----
    for (int t = 0; t < SEQ; t++) {
        CLUSTER_WAIT();

        const uint4* src = (const uint4*)&g_h[t & 1][gbase * UNITS];
        // issue ALL 8 LDGs up front (max MLP); p1 held in regs across MMA half 0
        uint4 p0[4], p1[4];
#pragma unroll
        for (int ii = 0; ii < 4; ii++) {
            int nrow = (tid >> 5) + ii * 8;
            p0[ii] = __ldcg(src + nrow * 64 + (L & 31));
            p1[ii] = __ldcg(src + nrow * 64 + 32 + (L & 31));
        }
        // unpack + STS half 0
#pragma unroll
        for (int ii = 0; ii < 4; ii++) {
            uint4 p = p0[ii];
            *(uint2*)(smem + OFF_BHI + soff0[ii]) = make_uint2(prmt(p.x, p.y, 0x5410u), prmt(p.z, p.w, 0x5410u));
            *(uint2*)(smem + OFF_BLO + soff0[ii]) = make_uint2(prmt(p.x, p.y, 0x7632u), prmt(p.z, p.w, 0x7632u));
        }
        __syncthreads();

        float acc[2][2][4];
#pragma unroll
        for (int mt = 0; mt < 2; mt++)
#pragma unroll
            for (int nb = 0; nb < 2; nb++)
#pragma unroll
                for (int e = 0; e < 4; e++) acc[mt][nb][e] = 0.0f;

        // ---- MMA half 0: ks 0..7 ----
#pragma unroll
        for (int ks = 0; ks < 8; ks++) {
            const uint32_t ka = ((uint32_t)(ks * 32) + koffA) ^ xA;
            const uint32_t kb = ((uint32_t)(ks * 32) + koffB) ^ xB;
            uint32_t Ah1[4], Al0[4], Al1[4], Bh[4], Bl[4];
            ldsm_x4(Bh, bHi + kb);
            ldsm_x4(Ah1, aHi1 + ka);
            ldsm_x4(Al0, aLo0 + ka);
            ldsm_x4(Al1, aLo1 + ka);
            ldsm_x4(Bl, bLo + kb);
#pragma unroll
            for (int nb = 0; nb < 2; nb++) {
                mma_bf16(acc[0][nb], AH0[ks][0], AH0[ks][1], AH0[ks][2], AH0[ks][3], Bh[2 * nb], Bh[2 * nb + 1]);
                mma_bf16(acc[1][nb], Ah1[0], Ah1[1], Ah1[2], Ah1[3], Bh[2 * nb], Bh[2 * nb + 1]);
                mma_bf16(acc[0][nb], Al0[0], Al0[1], Al0[2], Al0[3], Bh[2 * nb], Bh[2 * nb + 1]);
                mma_bf16(acc[1][nb], Al1[0], Al1[1], Al1[2], Al1[3], Bh[2 * nb], Bh[2 * nb + 1]);
                mma_bf16(acc[0][nb], AH0[ks][0], AH0[ks][1], AH0[ks][2], AH0[ks][3], Bl[2 * nb], Bl[2 * nb + 1]);
                mma_bf16(acc[1][nb], Ah1[0], Ah1[1], Ah1[2], Ah1[3], Bl[2 * nb], Bl[2 * nb + 1]);
            }
        }

        // unpack + STS half 1 (elements [128,256) — disjoint from half-0 reads)
#pragma unroll
        for (int ii = 0; ii < 4; ii++) {
            uint4 p = p1[ii];
            *(uint2*)(smem + OFF_BHI + soff1[ii]) = make_uint2(prmt(p.x, p.y, 0x5410u), prmt(p.z, p.w, 0x5410u));
            *(uint2*)(smem + OFF_BLO + soff1[ii]) = make_uint2(prmt(p.x, p.y, 0x7632u), prmt(p.z, p.w, 0x7632u));
        }
        __syncthreads();

        // ---- MMA half 1: ks 8..15 ----
#pragma unroll
        for (int ks = 8; ks < 16; ks++) {
            const uint32_t ka = ((uint32_t)(ks * 32) + koffA) ^ xA;
            const uint32_t kb = ((uint32_t)(ks * 32) + koffB) ^ xB;
            uint32_t Ah1[4], Al0[4], Al1[4], Bh[4], Bl[4];
            ldsm_x4(Bh, bHi + kb);
            ldsm_x4(Ah1, aHi1 + ka);
            ldsm_x4(Al0, aLo0 + ka);
            ldsm_x4(Al1, aLo1 + ka);
            ldsm_x4(Bl, bLo + kb);
#pragma unroll
            for (int nb = 0; nb < 2; nb++) {
                mma_bf16(acc[0][nb], AH0[ks][0], AH0[ks][1], AH0[ks][2], AH0[ks][3], Bh[2 * nb], Bh[2 * nb + 1]);
                mma_bf16(acc[1][nb], Ah1[0], Ah1[1], Ah1[2], Ah1[3], Bh[2 * nb], Bh[2 * nb + 1]);
                mma_bf16(acc[0][nb], Al0[0], Al0[1], Al0[2], Al0[3], Bh[2 * nb], Bh[2 * nb + 1]);
                mma_bf16(acc[1][nb], Al1[0], Al1[1], Al1[2], Al1[3], Bh[2 * nb], Bh[2 * nb + 1]);
                mma_bf16(acc[0][nb], AH0[ks][0], AH0[ks][1], AH0[ks][2], AH0[ks][3], Bl[2 * nb], Bl[2 * nb + 1]);
                mma_bf16(acc[1][nb], Ah1[0], Ah1[1], Ah1[2], Ah1[3], Bl[2 * nb], Bl[2 * nb + 1]);
            }
        }

        // ---- LSTM elementwise in registers ----
        {
            unsigned* dst = &g_h[(t + 1) & 1][0];
#pragma unroll
            for (int nb = 0; nb < 2; nb++) {
#pragma unroll
                for (int j = 0; j < 2; j++) {
                    const int e = nb * 2 + j;
                    float gi = acc[0][nb][j]     + wvi[e] + bi;
                    float gj = acc[0][nb][2 + j] + wvj[e] + bj;
                    float gf = acc[1][nb][j]     + wvf[e] + bf;
                    float go = acc[1][nb][2 + j] + wvo[e] + bo;
                    float nc = c_reg[e] * sigm(gf + 1.0f) + sigm(gi) * tanh_fast(gj);
                    c_reg[e] = nc;
                    float nh2 = tanh_fast(nc) * sigm(go);
                    __nv_bfloat16 hi = __float2bfloat16(nh2);
                    float rem = nh2 - __bfloat162float(hi);
                    __nv_bfloat16 lo = __float2bfloat16(rem);
                    unsigned packed = (unsigned)__bfloat16_as_ushort(hi) | ((unsigned)__bfloat16_as_ushort(lo) << 16);
                    __stcg(&dst[gidx[e]], packed);
                }
            }
        }
        CLUSTER_ARRIVE();

        // prefetch next tokens + Wx in the skew shadow
        {
            const int tp = (t + 1 < SEQ) ? (t + 1) : (SEQ - 1);
#pragma unroll
            for (int e = 0; e < 4; e++) {
                int bb = nh * 16 + ((e >> 1) ? 8 : 0) + (L & 3) * 2 + (e & 1);
                int tk = __ldg(&tokens[(gbase + bb) * SEQ + tp]);
                wvi[e] = wxi[tk]; wvj[e] = wxj[tk]; wvf[e] = wxf[tk]; wvo[e] = wxo[tk];
            }
        }
    }

    // ---- dense head ----
    CLUSTER_WAIT();
    {
        float* hs = (float*)(smem + OFF_AHI);
        const int bstart = r * 4;
        for (int i = tid; i < 4 * UNITS; i += NTHREADS) {
            unsigned p = __ldcg(&g_h[0][(gbase + bstart + (i >> 8)) * UNITS + (i & 255)]);
            hs[i] = __bfloat162float(__ushort_as_bfloat16((unsigned short)(p & 0xFFFFu))) +
                    __bfloat162float(__ushort_as_bfloat16((unsigned short)(p >> 16)));
        }
        __syncthreads();
        const int n    = tid & 127;
        const int pair = tid >> 7;
        float a0 = bd[n], a1 = bd[n];
        for (int k = 0; k < UNITS; k++) {
            float wv = Wd[k * NUM_CHARS + n];
            a0 += hs[(pair * 2 + 0) * 256 + k] * wv;
            a1 += hs[(pair * 2 + 1) * 256 + k] * wv;
        }
        out[(gbase + bstart + pair * 2 + 0) * NUM_CHARS + n] = a0;
        out[(gbase + bstart + pair * 2 + 1) * NUM_CHARS + n] = a1;
    }
}

// ---------------- host launcher ----------------
extern "C" void kernel_launch(void* const* d_in, const int* in_sizes, int n_in,
                              void* d_out, int out_size) {
    (void)in_sizes; (void)n_in; (void)out_size;
    const int*   tokens = (const int*)d_in[0];
    const float* Wx     = (const float*)d_in[1];
    const float* Wh     = (const float*)d_in[2];
    const float* b      = (const float*)d_in[3];
    const float* Wd     = (const float*)d_in[4];
    const float* bdn    = (const float*)d_in[5];
    float* out = (float*)d_out;

    cudaFuncSetAttribute(lstm_kernel, cudaFuncAttributeMaxDynamicSharedMemorySize, SMEM_TOTAL);

    init_kernel<<<256, 256>>>();
    lstm_kernel<<<NCTAS, NTHREADS, SMEM_TOTAL>>>(tokens, Wx, Wh, b, Wd, bdn, out);
}